// round 5
// baseline (speedup 1.0000x reference)
#include <cuda_runtime.h>
#include <cstdint>

typedef unsigned long long ull;

static constexpr int B_  = 1024;
static constexpr int T_  = 512;
static constexpr int DIN = 128;
static constexpr int H_  = 64;
static constexpr int O_  = 20;

// Precomputed layer-1 currents [b*T + t][64]
__device__ float g_cur1[(size_t)B_ * T_ * H_];

// ---------------------------------------------------------------------------
// packed f32x2 helpers
// ---------------------------------------------------------------------------
__device__ __forceinline__ ull ffma2(ull a, ull b, ull c) {
    ull d;
    asm("fma.rn.f32x2 %0, %1, %2, %3;" : "=l"(d) : "l"(a), "l"(b), "l"(c));
    return d;
}
__device__ __forceinline__ void addf2(ull& d, ull a, ull b) {
    asm("add.rn.f32x2 %0, %1, %2;" : "=l"(d) : "l"(a), "l"(b));
}
__device__ __forceinline__ ull pack2f(float x, float y) {
    ull d; asm("mov.b64 %0, {%1,%2};" : "=l"(d) : "f"(x), "f"(y)); return d;
}
__device__ __forceinline__ float2 unpack2f(ull v) {
    float2 r; asm("mov.b64 {%0,%1}, %2;" : "=f"(r.x), "=f"(r.y) : "l"(v)); return r;
}

// ---------------------------------------------------------------------------
// Kernel 1: cur1[r][n] = sum_k x[r][k]*W1[n][k] + b1[n]
// Tile: 128 rows x 64 cols, K=128 in 2 chunks of 64. 128 threads.
// A stored in smem as DUPLICATED f32 pairs [k][m] (ull) so the FFMA2
// broadcast operand needs no pack-MOVs. XOR column-group swizzle on stores.
// Per thread: 8m x 8n outputs; per k: 6 LDS.128 + 32 FFMA2 (84% density).
// ---------------------------------------------------------------------------
static constexpr int GEMM_SMEM = 64 * 128 * 8 + 64 * 64 * 4;  // 65536 + 16384

__global__ void __launch_bounds__(128) snn_gemm(
    const float* __restrict__ x,
    const float* __restrict__ W1,
    const float* __restrict__ b1)
{
    extern __shared__ char sm[];
    ull*   Ap = reinterpret_cast<ull*>(sm);            // [k][128] duplicated pairs
    float* Ws = reinterpret_cast<float*>(sm + 65536);  // [k][64]

    const int tid = threadIdx.x;
    const size_t rbase = (size_t)blockIdx.x * 128;
    const int m0 = (tid >> 3) * 8;      // 16 groups x 8 = 128
    const int n0 = (tid & 7) * 8;       //  8 groups x 8 = 64
    const int G  = m0 >> 3;             // 0..15
    const int Gn = n0 >> 3;             // 0..7

    ull acc[8][4];
#pragma unroll
    for (int i = 0; i < 8; i++)
#pragma unroll
        for (int j = 0; j < 4; j++) acc[i][j] = 0ull;

#pragma unroll 1
    for (int c = 0; c < 2; c++) {
        const int k0 = c * 64;

        // ---- stage A tile (128m x 64k) as duplicated pairs, swizzled ----
#pragma unroll
        for (int i = 0; i < 16; i++) {
            int idx = i * 128 + tid;       // 0..2047 float4s
            int m   = idx >> 4;            // 0..127
            int kv  = idx & 15;            // float4 index along k
            float4 v = *reinterpret_cast<const float4*>(
                x + (rbase + m) * DIN + k0 + kv * 4);
            int mg = m >> 3, ml = m & 7;
            int k  = kv * 4;
            Ap[(k + 0) * 128 + ((mg ^ ((k + 0) & 15)) << 3) + ml] = pack2f(v.x, v.x);
            Ap[(k + 1) * 128 + ((mg ^ ((k + 1) & 15)) << 3) + ml] = pack2f(v.y, v.y);
            Ap[(k + 2) * 128 + ((mg ^ ((k + 2) & 15)) << 3) + ml] = pack2f(v.z, v.z);
            Ap[(k + 3) * 128 + ((mg ^ ((k + 3) & 15)) << 3) + ml] = pack2f(v.w, v.w);
        }
        // ---- stage W tile (64n x 64k) transposed to [k][n], swizzled ----
#pragma unroll
        for (int i = 0; i < 8; i++) {
            int idx = i * 128 + tid;       // 0..1023 float4s
            int n   = idx >> 4;            // 0..63
            int kv  = idx & 15;
            float4 v = *reinterpret_cast<const float4*>(
                W1 + (size_t)n * DIN + k0 + kv * 4);
            int ng = n >> 3, nl = n & 7;
            int k  = kv * 4;
            Ws[(k + 0) * 64 + ((ng ^ ((k + 0) & 7)) << 3) + nl] = v.x;
            Ws[(k + 1) * 64 + ((ng ^ ((k + 1) & 7)) << 3) + nl] = v.y;
            Ws[(k + 2) * 64 + ((ng ^ ((k + 2) & 7)) << 3) + nl] = v.z;
            Ws[(k + 3) * 64 + ((ng ^ ((k + 3) & 7)) << 3) + nl] = v.w;
        }
        __syncthreads();

        // ---- compute ----
#pragma unroll 4
        for (int kk = 0; kk < 64; kk++) {
            const ulonglong2* ap = reinterpret_cast<const ulonglong2*>(
                Ap + kk * 128 + ((G ^ (kk & 15)) << 3));
            const ulonglong2* wp = reinterpret_cast<const ulonglong2*>(
                Ws + kk * 64 + ((Gn ^ (kk & 7)) << 3));
            ulonglong2 A0 = ap[0], A1 = ap[1], A2 = ap[2], A3 = ap[3];
            ulonglong2 B0 = wp[0], B1 = wp[1];
            ull a[8] = {A0.x, A0.y, A1.x, A1.y, A2.x, A2.y, A3.x, A3.y};
            ull w[4] = {B0.x, B0.y, B1.x, B1.y};
#pragma unroll
            for (int i = 0; i < 8; i++) {
#pragma unroll
                for (int j = 0; j < 4; j++)
                    acc[i][j] = ffma2(a[i], w[j], acc[i][j]);
            }
        }
        __syncthreads();
    }

    // ---- epilogue: bias + coalesced store ----
    float bias[8];
#pragma unroll
    for (int j = 0; j < 8; j++) bias[j] = __ldg(b1 + n0 + j);

#pragma unroll
    for (int i = 0; i < 8; i++) {
        float2 p0 = unpack2f(acc[i][0]);
        float2 p1 = unpack2f(acc[i][1]);
        float2 p2 = unpack2f(acc[i][2]);
        float2 p3 = unpack2f(acc[i][3]);
        float4 o0 = make_float4(p0.x + bias[0], p0.y + bias[1],
                                p1.x + bias[2], p1.y + bias[3]);
        float4 o1 = make_float4(p2.x + bias[4], p2.y + bias[5],
                                p3.x + bias[6], p3.y + bias[7]);
        float* dst = g_cur1 + (rbase + m0 + i) * H_ + n0;
        *reinterpret_cast<float4*>(dst)     = o0;
        *reinterpret_cast<float4*>(dst + 4) = o1;
    }
}

// ---------------------------------------------------------------------------
// Kernel 2: recurrent scan, software-pipelined one step.
// 8 warps/block, one warp per batch element; lane L owns neurons L, L+32.
// At iteration t we issue L1(t+1) (fma + 2 ballots) FIRST, then run the
// L2/L3 spike loops of step t — the two chains are independent, so the
// ballot/setp latency of one hides under the LDS loop of the other.
// ---------------------------------------------------------------------------
__device__ __forceinline__ float clip01(float v) {
    return fminf(fmaxf(v, 0.f), 1.f);
}

__global__ void __launch_bounds__(256) snn_scan(
    const float* __restrict__ W2, const float* __restrict__ b2,
    const float* __restrict__ beta2,
    const float* __restrict__ W3, const float* __restrict__ b3,
    const float* __restrict__ beta3,
    const float* __restrict__ beta1,
    float* __restrict__ out)
{
    __shared__ ull   sW2P[64 * 32];   // [i][lane] = (W2[lane][i], W2[lane+32][i])
    __shared__ float sW3T[64 * 32];   // [i][o] = W3[o][i]; cols >= 20 are 0

    const int tid  = threadIdx.x;
    const int lane = tid & 31;
    const int wid  = tid >> 5;
    const int b    = blockIdx.x * 8 + wid;

    for (int idx = tid; idx < 64 * 32; idx += 256) {
        int i = idx >> 5, l = idx & 31;
        sW2P[idx] = pack2f(W2[l * 64 + i], W2[(l + 32) * 64 + i]);
    }
    for (int idx = tid; idx < 64 * 32; idx += 256) sW3T[idx] = 0.f;
    __syncthreads();
    for (int idx = tid; idx < O_ * 64; idx += 256) {
        int o = idx >> 6, i = idx & 63;
        sW3T[i * 32 + o] = W3[idx];
    }
    __syncthreads();

    const float bt1a = clip01(beta1[lane]);
    const float bt1b = clip01(beta1[lane + 32]);
    const float bt2a = clip01(beta2[lane]);
    const float bt2b = clip01(beta2[lane + 32]);
    const ull   b2p  = pack2f(b2[lane], b2[lane + 32]);
    const float bt3  = (lane < O_) ? clip01(beta3[lane]) : 0.f;
    const float b3v  = (lane < O_) ? b3[lane] : 0.f;

    float m1a = 0.f, m1b = 0.f, m2a = 0.f, m2b = 0.f, m3 = 0.f;

    const float* src = g_cur1 + (size_t)b * T_ * H_ + lane;
    float* dst       = out + (size_t)b * T_ * O_;

    constexpr int PD = 8;
    float pa[PD], pb[PD];
#pragma unroll
    for (int i = 0; i < PD; i++) {
        pa[i] = src[i * H_];
        pb[i] = src[i * H_ + 32];
    }

    // ---- prologue: L1 for t = 0 ----
    {
        float ca = pa[0], cb = pb[0];
        if (PD < T_) { pa[0] = src[(size_t)PD * H_]; pb[0] = src[(size_t)PD * H_ + 32]; }
        float r;
        r   = (m1a > 1.f) ? 1.f : 0.f;
        m1a = fmaf(bt1a, m1a, ca) - r;
        r   = (m1b > 1.f) ? 1.f : 0.f;
        m1b = fmaf(bt1b, m1b, cb) - r;
    }
    unsigned l1 = __ballot_sync(0xffffffffu, m1a > 1.f);
    unsigned h1 = __ballot_sync(0xffffffffu, m1b > 1.f);
    ull mk1 = (ull)l1 | ((ull)h1 << 32);

#pragma unroll 2
    for (int t = 0; t < T_ - 1; t++) {
        ull mk = mk1;   // layer-1 spikes at step t

        // ---- L1 for step t+1 (independent chain; issued early) ----
        const int tn = t + 1;
        const int s  = tn & (PD - 1);
        float ca = pa[s], cb = pb[s];
        if (tn + PD < T_) {
            pa[s] = src[(size_t)(tn + PD) * H_];
            pb[s] = src[(size_t)(tn + PD) * H_ + 32];
        }
        float r;
        r   = (m1a > 1.f) ? 1.f : 0.f;
        m1a = fmaf(bt1a, m1a, ca) - r;
        r   = (m1b > 1.f) ? 1.f : 0.f;
        m1b = fmaf(bt1b, m1b, cb) - r;
        unsigned nl1 = __ballot_sync(0xffffffffu, m1a > 1.f);
        unsigned nh1 = __ballot_sync(0xffffffffu, m1b > 1.f);

        // ---- L2 for step t: sparse pair-sum (mask uniform over warp) ----
        ull acc = b2p;
        while (mk) {
            int i = __ffsll((long long)mk) - 1;
            mk &= mk - 1;
            addf2(acc, acc, sW2P[(i << 5) + lane]);
        }
        float2 c2 = unpack2f(acc);

        r   = (m2a > 1.f) ? 1.f : 0.f;
        m2a = fmaf(bt2a, m2a, c2.x) - r;
        r   = (m2b > 1.f) ? 1.f : 0.f;
        m2b = fmaf(bt2b, m2b, c2.y) - r;
        unsigned l2 = __ballot_sync(0xffffffffu, m2a > 1.f);
        unsigned h2 = __ballot_sync(0xffffffffu, m2b > 1.f);
        ull mk2 = (ull)l2 | ((ull)h2 << 32);

        // ---- L3 for step t (no reset; loop almost never entered) ----
        float acc3 = b3v;
        while (mk2) {
            int i = __ffsll((long long)mk2) - 1;
            mk2 &= mk2 - 1;
            acc3 += sW3T[(i << 5) + lane];
        }
        m3 = fmaf(bt3, m3, acc3);
        if (lane < O_) dst[(size_t)t * O_ + lane] = m3;

        mk1 = (ull)nl1 | ((ull)nh1 << 32);
    }

    // ---- tail: L2/L3 for step T-1 ----
    {
        ull mk = mk1;
        ull acc = b2p;
        while (mk) {
            int i = __ffsll((long long)mk) - 1;
            mk &= mk - 1;
            addf2(acc, acc, sW2P[(i << 5) + lane]);
        }
        float2 c2 = unpack2f(acc);
        float r;
        r   = (m2a > 1.f) ? 1.f : 0.f;
        m2a = fmaf(bt2a, m2a, c2.x) - r;
        r   = (m2b > 1.f) ? 1.f : 0.f;
        m2b = fmaf(bt2b, m2b, c2.y) - r;
        unsigned l2 = __ballot_sync(0xffffffffu, m2a > 1.f);
        unsigned h2 = __ballot_sync(0xffffffffu, m2b > 1.f);
        ull mk2 = (ull)l2 | ((ull)h2 << 32);
        float acc3 = b3v;
        while (mk2) {
            int i = __ffsll((long long)mk2) - 1;
            mk2 &= mk2 - 1;
            acc3 += sW3T[(i << 5) + lane];
        }
        m3 = fmaf(bt3, m3, acc3);
        if (lane < O_) dst[(size_t)(T_ - 1) * O_ + lane] = m3;
    }
}

// ---------------------------------------------------------------------------
// Launch
// ---------------------------------------------------------------------------
extern "C" void kernel_launch(void* const* d_in, const int* in_sizes, int n_in,
                              void* d_out, int out_size)
{
    const float* x     = (const float*)d_in[0];
    const float* W1    = (const float*)d_in[1];
    const float* b1    = (const float*)d_in[2];
    const float* beta1 = (const float*)d_in[3];
    const float* W2    = (const float*)d_in[4];
    const float* b2    = (const float*)d_in[5];
    const float* beta2 = (const float*)d_in[6];
    const float* W3    = (const float*)d_in[7];
    const float* b3    = (const float*)d_in[8];
    const float* beta3 = (const float*)d_in[9];
    float* out = (float*)d_out;

    const int R = in_sizes[0] / DIN;     // B*T = 524288

    static bool attr_set = false;
    if (!attr_set) {
        cudaFuncSetAttribute(snn_gemm,
                             cudaFuncAttributeMaxDynamicSharedMemorySize, GEMM_SMEM);
        attr_set = true;
    }
    snn_gemm<<<R / 128, 128, GEMM_SMEM>>>(x, W1, b1);
    snn_scan<<<B_ / 8, 256>>>(W2, b2, beta2, W3, b3, beta3, beta1, out);
}

// round 6
// speedup vs baseline: 3.0557x; 3.0557x over previous
#include <cuda_runtime.h>
#include <cstdint>

typedef unsigned long long ull;

static constexpr int B_  = 1024;
static constexpr int T_  = 512;
static constexpr int DIN = 128;
static constexpr int H_  = 64;
static constexpr int O_  = 20;

// Precomputed layer-1 currents [b*T + t][64]
__device__ float g_cur1[(size_t)B_ * T_ * H_];

// ---------------------------------------------------------------------------
// helpers
// ---------------------------------------------------------------------------
__device__ __forceinline__ uint32_t smem_u32(const void* p) {
    uint32_t a;
    asm("{ .reg .u64 t; cvta.to.shared.u64 t, %1; cvt.u32.u64 %0, t; }"
        : "=r"(a) : "l"(p));
    return a;
}
__device__ __forceinline__ ull pack2f(float x, float y) {
    ull d; asm("mov.b64 %0, {%1,%2};" : "=l"(d) : "f"(x), "f"(y)); return d;
}
__device__ __forceinline__ float2 unpack2f(ull v) {
    float2 r; asm("mov.b64 {%0,%1}, %2;" : "=f"(r.x), "=f"(r.y) : "l"(v)); return r;
}
__device__ __forceinline__ void addf2(ull& d, ull a, ull b) {
    asm("add.rn.f32x2 %0, %1, %2;" : "=l"(d) : "l"(a), "l"(b));
}
// pack (lo -> bits[15:0], hi -> bits[31:16]) as bf16x2, round-to-nearest
__device__ __forceinline__ uint32_t pack_bf16x2(float lo, float hi) {
    uint32_t r;
    asm("cvt.rn.satfinite.bf16x2.f32 %0, %2, %1;" : "=r"(r) : "f"(lo), "f"(hi));
    return r;
}
__device__ __forceinline__ void ldsm4(uint32_t* r, uint32_t addr) {
    asm volatile("ldmatrix.sync.aligned.m8n8.x4.shared.b16 {%0,%1,%2,%3}, [%4];"
                 : "=r"(r[0]), "=r"(r[1]), "=r"(r[2]), "=r"(r[3]) : "r"(addr));
}
__device__ __forceinline__ void mma16816(float* c, const uint32_t* a,
                                         const uint32_t* b) {
    asm volatile(
        "mma.sync.aligned.m16n8k16.row.col.f32.bf16.bf16.f32 "
        "{%0,%1,%2,%3}, {%4,%5,%6,%7}, {%8,%9}, {%0,%1,%2,%3};"
        : "+f"(c[0]), "+f"(c[1]), "+f"(c[2]), "+f"(c[3])
        : "r"(a[0]), "r"(a[1]), "r"(a[2]), "r"(a[3]), "r"(b[0]), "r"(b[1]));
}

// ---------------------------------------------------------------------------
// Kernel 1: layer-1 GEMM via legacy HMMA (mma.sync m16n8k16 bf16, fp32 acc),
// 3-term bf16 split for fp32-level accuracy.
// Tile/block: M=128 rows of x, N=64, K=128. 256 threads (8 warps).
// smem rows padded to 136 bf16 (272 B) -> ldmatrix conflict-free.
// ---------------------------------------------------------------------------
static constexpr int SROW = 136;                    // bf16 elems per smem row
static constexpr int AH_OFF = 0;                    // u32-word offsets
static constexpr int AL_OFF = 128 * (SROW / 2);     // 8704
static constexpr int BH_OFF = 2 * AL_OFF;           // 17408
static constexpr int BL_OFF = BH_OFF + 64 * (SROW / 2);
static constexpr int GEMM_WORDS = BL_OFF + 64 * (SROW / 2);
static constexpr int GEMM_SMEM  = GEMM_WORDS * 4;   // 104448 B

__global__ void __launch_bounds__(256) snn_gemm_mma(
    const float* __restrict__ x,
    const float* __restrict__ W1,
    const float* __restrict__ b1)
{
    extern __shared__ uint32_t sm[];
    __shared__ float b1s[64];

    const int tid  = threadIdx.x;
    const int lane = tid & 31;
    const int wid  = tid >> 5;
    const size_t rbase = (size_t)blockIdx.x * 128;

    if (tid < 64) b1s[tid] = b1[tid];

    // ---- convert x tile (128 x 128 f32) -> bf16 hi/lo smem ----
#pragma unroll
    for (int it = 0; it < 16; it++) {
        int idx = it * 256 + tid;           // 0..4095 float4s
        int row = idx >> 5;                 // 0..127
        int c4  = idx & 31;                 // float4 col
        float4 v = *reinterpret_cast<const float4*>(x + (rbase + row) * DIN + c4 * 4);
        uint32_t h01 = pack_bf16x2(v.x, v.y);
        uint32_t h23 = pack_bf16x2(v.z, v.w);
        float h0 = __uint_as_float(h01 << 16), h1 = __uint_as_float(h01 & 0xffff0000u);
        float h2 = __uint_as_float(h23 << 16), h3 = __uint_as_float(h23 & 0xffff0000u);
        uint32_t l01 = pack_bf16x2(v.x - h0, v.y - h1);
        uint32_t l23 = pack_bf16x2(v.z - h2, v.w - h3);
        int w = row * (SROW / 2) + c4 * 2;
        *reinterpret_cast<ull*>(&sm[AH_OFF + w]) = ((ull)h23 << 32) | h01;
        *reinterpret_cast<ull*>(&sm[AL_OFF + w]) = ((ull)l23 << 32) | l01;
    }
    // ---- convert W1 (64 x 128 f32) -> bf16 hi/lo smem ----
#pragma unroll
    for (int it = 0; it < 8; it++) {
        int idx = it * 256 + tid;           // 0..2047
        int row = idx >> 5;                 // 0..63
        int c4  = idx & 31;
        float4 v = *reinterpret_cast<const float4*>(W1 + (size_t)row * DIN + c4 * 4);
        uint32_t h01 = pack_bf16x2(v.x, v.y);
        uint32_t h23 = pack_bf16x2(v.z, v.w);
        float h0 = __uint_as_float(h01 << 16), h1 = __uint_as_float(h01 & 0xffff0000u);
        float h2 = __uint_as_float(h23 << 16), h3 = __uint_as_float(h23 & 0xffff0000u);
        uint32_t l01 = pack_bf16x2(v.x - h0, v.y - h1);
        uint32_t l23 = pack_bf16x2(v.z - h2, v.w - h3);
        int w = row * (SROW / 2) + c4 * 2;
        *reinterpret_cast<ull*>(&sm[BH_OFF + w]) = ((ull)h23 << 32) | h01;
        *reinterpret_cast<ull*>(&sm[BL_OFF + w]) = ((ull)l23 << 32) | l01;
    }
    __syncthreads();

    // ---- MMA mainloop ----
    const uint32_t sbase = smem_u32(sm);
    const int m0  = wid * 16;
    const int mat = lane >> 3, mr = lane & 7;
    // A lane address pieces: rows (mat&1)*8+mr, k offset (mat>>1)*8
    const uint32_t aoff = (uint32_t)((m0 + (mat & 1) * 8 + mr) * SROW +
                                     (mat >> 1) * 8) * 2;
    // B lane address pieces: n row (mat>>1)*8+mr, k offset (mat&1)*8
    const uint32_t boff = (uint32_t)(((mat >> 1) * 8 + mr) * SROW +
                                     (mat & 1) * 8) * 2;

    float acc[8][4];
#pragma unroll
    for (int i = 0; i < 8; i++)
#pragma unroll
        for (int j = 0; j < 4; j++) acc[i][j] = 0.f;

    const uint32_t Abase[3] = { sbase + AH_OFF * 4, sbase + AH_OFF * 4,
                                sbase + AL_OFF * 4 };
    const uint32_t Bbase[3] = { sbase + BH_OFF * 4, sbase + BL_OFF * 4,
                                sbase + BH_OFF * 4 };

#pragma unroll
    for (int t = 0; t < 3; t++) {
        const uint32_t aB = Abase[t] + aoff;
        const uint32_t bB = Bbase[t] + boff;
#pragma unroll
        for (int kc = 0; kc < 8; kc++) {
            uint32_t a[4];
            ldsm4(a, aB + kc * 32);
#pragma unroll
            for (int np = 0; np < 4; np++) {
                uint32_t b[4];
                ldsm4(b, bB + (uint32_t)(np * 16 * SROW) * 2 + kc * 32);
                mma16816(acc[np * 2 + 0], a, b + 0);
                mma16816(acc[np * 2 + 1], a, b + 2);
            }
        }
    }

    // ---- epilogue: bias + store ----
    const int g = lane >> 2, q = lane & 3;
#pragma unroll
    for (int np = 0; np < 4; np++) {
#pragma unroll
        for (int h = 0; h < 2; h++) {
            const float* a4 = acc[np * 2 + h];
            int col = np * 16 + h * 8 + 2 * q;
            float2 bv = *reinterpret_cast<const float2*>(&b1s[col]);
            float2 o0 = make_float2(a4[0] + bv.x, a4[1] + bv.y);
            float2 o1 = make_float2(a4[2] + bv.x, a4[3] + bv.y);
            float* d0 = g_cur1 + (rbase + m0 + g) * H_ + col;
            float* d1 = g_cur1 + (rbase + m0 + g + 8) * H_ + col;
            *reinterpret_cast<float2*>(d0) = o0;
            *reinterpret_cast<float2*>(d1) = o1;
        }
    }
}

// ---------------------------------------------------------------------------
// Kernel 2: recurrent scan. 2 warps/block, one warp per batch element.
// Lane L owns neurons L, L+32. Software-pipelined: L1(t+1) issued before the
// L2 gather of step t. L2 gather is branch-free: 6 predicated slots + rare
// warp-uniform tail. Full unroll 8 keeps the prefetch ring in registers.
// ---------------------------------------------------------------------------
__device__ __forceinline__ float clip01(float v) {
    return fminf(fmaxf(v, 0.f), 1.f);
}

__global__ void __launch_bounds__(64, 8) snn_scan(
    const float* __restrict__ W2, const float* __restrict__ b2,
    const float* __restrict__ beta2,
    const float* __restrict__ W3, const float* __restrict__ b3,
    const float* __restrict__ beta3,
    const float* __restrict__ beta1,
    float* __restrict__ out)
{
    __shared__ ull   sW2P[64 * 32];   // [i][lane] = (W2[lane][i], W2[lane+32][i])
    __shared__ float sW3T[64 * 32];   // [i][o] = W3[o][i]; cols >= 20 are 0

    const int tid  = threadIdx.x;
    const int lane = tid & 31;
    const int wid  = tid >> 5;
    const int b    = blockIdx.x * 2 + wid;

    for (int idx = tid; idx < 64 * 32; idx += 64) {
        int i = idx >> 5, l = idx & 31;
        sW2P[idx] = pack2f(W2[l * 64 + i], W2[(l + 32) * 64 + i]);
    }
    for (int idx = tid; idx < 64 * 32; idx += 64) sW3T[idx] = 0.f;
    __syncthreads();
    for (int idx = tid; idx < O_ * 64; idx += 64) {
        int o = idx >> 6, i = idx & 63;
        sW3T[i * 32 + o] = W3[idx];
    }
    __syncthreads();

    const float bt1a = clip01(beta1[lane]);
    const float bt1b = clip01(beta1[lane + 32]);
    const float bt2a = clip01(beta2[lane]);
    const float bt2b = clip01(beta2[lane + 32]);
    const ull   b2p  = pack2f(b2[lane], b2[lane + 32]);
    const float bt3  = (lane < O_) ? clip01(beta3[lane]) : 0.f;
    const float b3v  = (lane < O_) ? b3[lane] : 0.f;

    float m1a = 0.f, m1b = 0.f, m2a = 0.f, m2b = 0.f, m3 = 0.f;

    const float* src = g_cur1 + (size_t)b * T_ * H_ + lane;
    float* dst       = out + (size_t)b * T_ * O_;

    constexpr int PD = 8;
    float pa[PD], pb[PD];
#pragma unroll
    for (int i = 0; i < PD; i++) {
        pa[i] = src[i * H_];
        pb[i] = src[i * H_ + 32];
    }

    // ---- prologue: L1 spikes for t = 0 (consumes cur1(0) = pa[0]) ----
    ull mk1;
    {
        float ca = pa[0], cb = pb[0];
        pa[0] = src[(size_t)PD * H_];
        pb[0] = src[(size_t)PD * H_ + 32];
        m1a = fmaf(bt1a, m1a, ca);
        m1b = fmaf(bt1b, m1b, cb);
        unsigned lo = __ballot_sync(0xffffffffu, m1a > 1.f);
        unsigned hi = __ballot_sync(0xffffffffu, m1b > 1.f);
        mk1 = (ull)lo | ((ull)hi << 32);
    }

#pragma unroll 8
    for (int t = 0; t < T_; t++) {
        const ull mk = mk1;     // layer-1 spikes at step t

        // ---- L1 for step t+1 (independent chain, issued early) ----
        // (at t = T_-1 this computes harmless garbage that is never used)
        const int tn = t + 1;
        const int s  = tn & (PD - 1);
        float ca = pa[s], cb = pb[s];
        if (tn + PD < T_) {
            pa[s] = src[(size_t)(tn + PD) * H_];
            pb[s] = src[(size_t)(tn + PD) * H_ + 32];
        }
        float r;
        r   = (m1a > 1.f) ? 1.f : 0.f;
        m1a = fmaf(bt1a, m1a, ca) - r;
        r   = (m1b > 1.f) ? 1.f : 0.f;
        m1b = fmaf(bt1b, m1b, cb) - r;
        unsigned nl = __ballot_sync(0xffffffffu, m1a > 1.f);
        unsigned nh = __ballot_sync(0xffffffffu, m1b > 1.f);

        // ---- L2 for step t: branch-free bounded gather ----
        ull m = mk;
        const int n = __popcll(mk);
        ull acc0 = b2p, acc1 = 0ull;
#pragma unroll
        for (int j = 0; j < 6; j++) {
            int i = __ffsll((long long)m) - 1;
            m &= m - 1;
            ull w = sW2P[((i & 63) << 5) + lane];
            ull sel = (j < n) ? w : 0ull;
            if (j & 1) addf2(acc1, acc1, sel);
            else       addf2(acc0, acc0, sel);
        }
        while (m) {             // rare (>6 spikes), warp-uniform
            int i = __ffsll((long long)m) - 1;
            m &= m - 1;
            addf2(acc0, acc0, sW2P[(i << 5) + lane]);
        }
        addf2(acc0, acc0, acc1);
        float2 c2 = unpack2f(acc0);

        r   = (m2a > 1.f) ? 1.f : 0.f;
        m2a = fmaf(bt2a, m2a, c2.x) - r;
        r   = (m2b > 1.f) ? 1.f : 0.f;
        m2b = fmaf(bt2b, m2b, c2.y) - r;
        unsigned l2 = __ballot_sync(0xffffffffu, m2a > 1.f);
        unsigned h2 = __ballot_sync(0xffffffffu, m2b > 1.f);
        ull mk2 = (ull)l2 | ((ull)h2 << 32);

        // ---- L3 for step t (no reset; loop almost never entered) ----
        float acc3 = b3v;
        while (mk2) {
            int i = __ffsll((long long)mk2) - 1;
            mk2 &= mk2 - 1;
            acc3 += sW3T[(i << 5) + lane];
        }
        m3 = fmaf(bt3, m3, acc3);
        if (lane < O_) dst[(size_t)t * O_ + lane] = m3;

        mk1 = (ull)nl | ((ull)nh << 32);
    }
}

// ---------------------------------------------------------------------------
// Launch
// ---------------------------------------------------------------------------
extern "C" void kernel_launch(void* const* d_in, const int* in_sizes, int n_in,
                              void* d_out, int out_size)
{
    const float* x     = (const float*)d_in[0];
    const float* W1    = (const float*)d_in[1];
    const float* b1    = (const float*)d_in[2];
    const float* beta1 = (const float*)d_in[3];
    const float* W2    = (const float*)d_in[4];
    const float* b2    = (const float*)d_in[5];
    const float* beta2 = (const float*)d_in[6];
    const float* W3    = (const float*)d_in[7];
    const float* b3    = (const float*)d_in[8];
    const float* beta3 = (const float*)d_in[9];
    float* out = (float*)d_out;

    const int R = in_sizes[0] / DIN;     // B*T = 524288

    cudaFuncSetAttribute(snn_gemm_mma,
                         cudaFuncAttributeMaxDynamicSharedMemorySize, GEMM_SMEM);
    snn_gemm_mma<<<R / 128, 256, GEMM_SMEM>>>(x, W1, b1);
    snn_scan<<<B_ / 2, 64>>>(W2, b2, beta2, W3, b3, beta3, beta1, out);
}